// round 11
// baseline (speedup 1.0000x reference)
#include <cuda_runtime.h>
#include <cuda_bf16.h>
#include <cstdint>

// ============================================================
// PINN fwd + 1st/2nd derivatives via mma.sync (HMMA) bf16 hi/lo
//   CTA: 16 samples, 512 threads / 16 warps.
//   Warp w: j-tile pair p=w>>1 (32 rows of M) x ct-parity h=w&1
//   (ct = 2q+h  <=>  quantity q, sample half h). Each ldmatrix.x4
//   pair feeds 12 MMAs; all 7 quantities of a sample are thread-local.
//   3 passes Whi*Shi + Whi*Slo + Wlo*Shi accumulated in fp32 registers.
// ============================================================

#define THREADS 512
#define SB 16
#define BROW 240              // bytes per state row (112*2 = 224 + 16 pad)
#define BHALF (256 * BROW)    // 61440 per half

#define SM_BHI 0
#define SM_BLO BHALF
#define SM_W4   (2 * BHALF)         // 122880 : w4t[o][i] f32, 2048 B
#define SM_BIAS (SM_W4 + 2048)      // 124928 : b1,b2,b3 f32, 3072 B
#define SM_TOTAL (SM_BIAS + 3072)   // 128000
// final-layer fp32 state overlays BHI/BLO: S3f[c][i], row stride 1040 B
#define S3STRIDE 260                // floats per row (256 + 4 pad)

// pre-transposed weights: WtH/WtL[L][j][i] bf16, j,i in [0,256)
__device__ uint16_t g_WtH[3 * 256 * 256];
__device__ uint16_t g_WtL[3 * 256 * 256];

__device__ __forceinline__ uint32_t smem_u32(const void* p) {
    uint32_t a;
    asm("{ .reg .u64 t; cvta.to.shared.u64 t, %1; cvt.u32.u64 %0, t; }"
        : "=r"(a) : "l"(p));
    return a;
}
__device__ __forceinline__ void ldmB4(uint32_t* b, uint32_t addr) {
    asm volatile("ldmatrix.sync.aligned.m8n8.x4.trans.shared.b16 {%0,%1,%2,%3}, [%4];"
                 : "=r"(b[0]), "=r"(b[1]), "=r"(b[2]), "=r"(b[3]) : "r"(addr));
}
__device__ __forceinline__ void mma16816(float* d, const uint32_t* a,
                                         uint32_t b0, uint32_t b1) {
    asm volatile(
        "mma.sync.aligned.m16n8k16.row.col.f32.bf16.bf16.f32 "
        "{%0,%1,%2,%3}, {%4,%5,%6,%7}, {%8,%9}, {%0,%1,%2,%3};"
        : "+f"(d[0]), "+f"(d[1]), "+f"(d[2]), "+f"(d[3])
        : "r"(a[0]), "r"(a[1]), "r"(a[2]), "r"(a[3]), "r"(b0), "r"(b1));
}
__device__ __forceinline__ uint32_t pk2(float a, float b) {
    return (uint32_t)__bfloat16_as_ushort(__float2bfloat16(a)) |
           ((uint32_t)__bfloat16_as_ushort(__float2bfloat16(b)) << 16);
}

// ---------------- prep: W[L] (i-major) -> Wt[L][j][i] bf16 hi/lo ----------
__global__ void __launch_bounds__(256) prep_kernel(
    const float* __restrict__ W1, const float* __restrict__ W2,
    const float* __restrict__ W3)
{
    int idx = blockIdx.x * 256 + threadIdx.x;   // = L*65536 + j*256 + i
    int L = idx >> 16;
    int j = (idx >> 8) & 255;
    int i = idx & 255;
    const float* W = (L == 0) ? W1 : ((L == 1) ? W2 : W3);
    float v = W[i * 256 + j];
    __nv_bfloat16 hb = __float2bfloat16(v);
    float lo = v - __bfloat162float(hb);
    g_WtH[idx] = __bfloat16_as_ushort(hb);
    g_WtL[idx] = __bfloat16_as_ushort(__float2bfloat16(lo));
}

// ---------------- main kernel ----------------
__global__ void __launch_bounds__(THREADS, 1) pinn_mma_kernel(
    const float* __restrict__ x,
    const float* __restrict__ W0, const float* __restrict__ b0_,
    const float* __restrict__ b1_, const float* __restrict__ b2_,
    const float* __restrict__ b3_,
    const float* __restrict__ W4, const float* __restrict__ b4,
    const float* __restrict__ lb, const float* __restrict__ ub,
    float* __restrict__ out, int N)
{
    extern __shared__ char sm[];
    const uint32_t smb = smem_u32(sm);
    const int tid  = threadIdx.x;
    const int warp = tid >> 5, lane = tid & 31;
    const int g = lane >> 2, tg = lane & 3;
    const int h  = warp & 1;             // ct parity = sample half
    const int wp = warp >> 1;            // j-tile pair index (0..7)
    const int s0 = blockIdx.x * SB;

    // stage W4 transposed (w4t[o][i]) and hidden biases
    ((float*)(sm + SM_W4))[(tid & 1) * 256 + (tid >> 1)] = W4[tid];
    if (tid < 256) {
        ((float*)(sm + SM_BIAS))[tid]       = b1_[tid];
        ((float*)(sm + SM_BIAS))[256 + tid] = b2_[tid];
        ((float*)(sm + SM_BIAS))[512 + tid] = b3_[tid];
    }

    // ---------- layer 0: 3 -> 256 (SIMT), write bf16 hi/lo state ----------
    {
        float lbv[3], sk[3];
#pragma unroll
        for (int k = 0; k < 3; k++) { lbv[k] = lb[k]; sk[k] = 2.0f / (ub[k] - lb[k]); }
        const int j = tid & 255;
        const int hh = tid >> 8;         // sample-half split across 512 threads
        float w[3];
#pragma unroll
        for (int k = 0; k < 3; k++) w[k] = W0[k * 256 + j];
        const float bj = b0_[j];
        float zj[3], Szl = 0.0f;
#pragma unroll
        for (int k = 0; k < 3; k++) { zj[k] = w[k] * sk[k]; Szl += zj[k]; }
#pragma unroll
        for (int spp = 0; spp < 4; spp++) {
            const int sp = hh * 4 + spp;
            float v[2][7];
#pragma unroll
            for (int p = 0; p < 2; p++) {
                const int s = 2 * sp + p;
                float xn0 = sk[0] * (x[(s0 + s) * 3 + 0] - lbv[0]) - 1.0f;
                float xn1 = sk[1] * (x[(s0 + s) * 3 + 1] - lbv[1]) - 1.0f;
                float xn2 = sk[2] * (x[(s0 + s) * 3 + 2] - lbv[2]) - 1.0f;
                float z = bj + w[0] * xn0 + w[1] * xn1 + w[2] * xn2;
                float t = tanhf(z);
                float gg = 1.0f - t * t;
                float u = -2.0f * t * gg * Szl;
                v[p][0] = t;
#pragma unroll
                for (int k = 0; k < 3; k++) { v[p][1 + k] = gg * zj[k]; v[p][4 + k] = u * zj[k]; }
            }
#pragma unroll
            for (int q = 0; q < 7; q++) {
                const int off = j * BROW + 32 * q + 4 * sp;   // col = 16q + 2sp
                float h0 = __bfloat162float(__float2bfloat16(v[0][q]));
                float h1 = __bfloat162float(__float2bfloat16(v[1][q]));
                *(uint32_t*)(sm + SM_BHI + off) = pk2(v[0][q], v[1][q]);
                *(uint32_t*)(sm + SM_BLO + off) = pk2(v[0][q] - h0, v[1][q] - h1);
            }
        }
    }
    __syncthreads();

    // ---------- hidden layers 1..3 via mma.sync ----------
#pragma unroll 1
    for (int L = 0; L < 3; L++) {
        const uint16_t* __restrict__ WH = g_WtH + L * 65536;
        const uint16_t* __restrict__ WL = g_WtL + L * 65536;

        float acc[2][7][4];                  // [j-tile][quantity][frag]
#pragma unroll
        for (int jj = 0; jj < 2; jj++)
#pragma unroll
            for (int q = 0; q < 7; q++)
#pragma unroll
                for (int d = 0; d < 4; d++) acc[jj][q][d] = 0.0f;

#pragma unroll 1
        for (int kb = 0; kb < 8; kb++) {
            uint32_t aH[2][2][4], aL[2][2][4];
#pragma unroll
            for (int jj = 0; jj < 2; jj++) {
                const int jbase = (wp * 2 + jj) * 16;
#pragma unroll
                for (int kk = 0; kk < 2; kk++) {
                    const int i0 = kb * 32 + kk * 16 + 2 * tg;
                    const uint16_t* pH = WH + (jbase + g) * 256 + i0;
                    const uint16_t* pL = WL + (jbase + g) * 256 + i0;
                    aH[jj][kk][0] = *(const uint32_t*)(pH);
                    aH[jj][kk][1] = *(const uint32_t*)(pH + 8 * 256);
                    aH[jj][kk][2] = *(const uint32_t*)(pH + 8);
                    aH[jj][kk][3] = *(const uint32_t*)(pH + 8 * 256 + 8);
                    aL[jj][kk][0] = *(const uint32_t*)(pL);
                    aL[jj][kk][1] = *(const uint32_t*)(pL + 8 * 256);
                    aL[jj][kk][2] = *(const uint32_t*)(pL + 8);
                    aL[jj][kk][3] = *(const uint32_t*)(pL + 8 * 256 + 8);
                }
            }
#pragma unroll
            for (int q = 0; q < 7; q++) {
                const int ct = 2 * q + h;
                const uint32_t baddr = smb + SM_BHI +
                    (uint32_t)(kb * 32 * BROW) + (uint32_t)(lane * BROW) + ct * 16;
                uint32_t bh[4], bl[4];
                ldmB4(bh, baddr);
                ldmB4(bl, baddr + BHALF);
#pragma unroll
                for (int jj = 0; jj < 2; jj++) {
                    mma16816(acc[jj][q], aH[jj][0], bh[0], bh[1]);
                    mma16816(acc[jj][q], aH[jj][1], bh[2], bh[3]);
                    mma16816(acc[jj][q], aH[jj][0], bl[0], bl[1]);
                    mma16816(acc[jj][q], aH[jj][1], bl[2], bl[3]);
                    mma16816(acc[jj][q], aL[jj][0], bh[0], bh[1]);
                    mma16816(acc[jj][q], aL[jj][1], bh[2], bh[3]);
                }
            }
        }
        __syncthreads();   // all reads of old state done

        // ---------- elementwise (thread-local) ----------
        const float* bias = (const float*)(sm + SM_BIAS) + L * 256;
        const bool last = (L == 2);
        const int se = 8 * h + 2 * tg;       // even sample index owned by this thread
#pragma unroll
        for (int jj = 0; jj < 2; jj++) {
#pragma unroll
            for (int r = 0; r < 2; r++) {
                const int j = (wp * 2 + jj) * 16 + g + 8 * r;
                const float bj = bias[j];
                float v[2][7];
#pragma unroll
                for (int p = 0; p < 2; p++) {
                    const int d = 2 * r + p;
                    float zh = acc[jj][0][d] + bj;
                    float z0 = acc[jj][1][d];
                    float z1 = acc[jj][2][d];
                    float z2 = acc[jj][3][d];
                    float t0 = acc[jj][4][d];
                    float t1 = acc[jj][5][d];
                    float t2 = acc[jj][6][d];
                    float t = tanhf(zh);
                    float gg = 1.0f - t * t;
                    float Sz = z0 + z1 + z2;
                    float u = -2.0f * t * gg * Sz;
                    v[p][0] = t;
                    v[p][1] = gg * z0; v[p][2] = gg * z1; v[p][3] = gg * z2;
                    v[p][4] = u * z0 + gg * t0;
                    v[p][5] = u * z1 + gg * t1;
                    v[p][6] = u * z2 + gg * t2;
                }
                if (!last) {
#pragma unroll
                    for (int q = 0; q < 7; q++) {
                        const int off = j * BROW + (16 * q + se) * 2;
                        float h0 = __bfloat162float(__float2bfloat16(v[0][q]));
                        float h1 = __bfloat162float(__float2bfloat16(v[1][q]));
                        *(uint32_t*)(sm + SM_BHI + off) = pk2(v[0][q], v[1][q]);
                        *(uint32_t*)(sm + SM_BLO + off) = pk2(v[0][q] - h0, v[1][q] - h1);
                    }
                } else {
#pragma unroll
                    for (int q = 0; q < 7; q++) {
                        ((float*)sm)[(16 * q + se) * S3STRIDE + j]     = v[0][q];
                        ((float*)sm)[(16 * q + se + 1) * S3STRIDE + j] = v[1][q];
                    }
                }
            }
        }
        __syncthreads();
    }

    // ---------- final layer: 256 -> 2 ----------
    if (tid < 224) {
        const int o = tid & 1, c = tid >> 1;
        const float4* row = reinterpret_cast<const float4*>(sm + (size_t)c * (S3STRIDE * 4));
        const float4* wr  = reinterpret_cast<const float4*>(sm + SM_W4 + o * 1024);
        float sum = 0.0f;
#pragma unroll 8
        for (int i4 = 0; i4 < 64; i4++) {
            float4 a = row[i4];
            float4 b = wr[i4];
            sum += a.x * b.x + a.y * b.y + a.z * b.z + a.w * b.w;
        }
        const int q = c >> 4, s = c & 15;
        const int n = s0 + s;
        if (q == 0) {
            out[n * 2 + o] = sum + b4[o];
        } else if (q < 4) {
            out[2 * N + o * 3 * N + n * 3 + (q - 1)] = sum;
        } else {
            out[8 * N + o * 3 * N + n * 3 + (q - 4)] = sum;
        }
    }
}

extern "C" void kernel_launch(void* const* d_in, const int* in_sizes, int n_in,
                              void* d_out, int out_size)
{
    const float* x  = (const float*)d_in[0];
    const float* W0 = (const float*)d_in[1];
    const float* b0 = (const float*)d_in[2];
    const float* W1 = (const float*)d_in[3];
    const float* b1 = (const float*)d_in[4];
    const float* W2 = (const float*)d_in[5];
    const float* b2 = (const float*)d_in[6];
    const float* W3 = (const float*)d_in[7];
    const float* b3 = (const float*)d_in[8];
    const float* W4 = (const float*)d_in[9];
    const float* b4 = (const float*)d_in[10];
    const float* lb = (const float*)d_in[11];
    const float* ub = (const float*)d_in[12];
    float* out = (float*)d_out;

    const int N = in_sizes[0] / 3;          // 32768

    prep_kernel<<<3 * 256 * 256 / 256, 256>>>(W1, W2, W3);

    cudaFuncSetAttribute(pinn_mma_kernel,
                         cudaFuncAttributeMaxDynamicSharedMemorySize, SM_TOTAL);
    pinn_mma_kernel<<<N / SB, THREADS, SM_TOTAL>>>(
        x, W0, b0, b1, b2, b3, W4, b4, lb, ub, out, N);
}

// round 12
// speedup vs baseline: 1.5921x; 1.5921x over previous
#include <cuda_runtime.h>
#include <cuda_bf16.h>
#include <cstdint>

// ============================================================
// PINN fwd + 1st/2nd derivatives via mma.sync (HMMA) bf16 hi/lo
//   CTA: 16 samples, 512 threads / 16 warps.
//   Warp w: j-tile pair wp=w>>1 (32 M-rows) x ct-parity h=w&1
//   (ct = 2q+h <=> quantity q, sample half h). Each ldmatrix.x4 pair
//   feeds 12 MMAs; all 7 quantities of a sample stay thread-local.
//   A is stored FRAGMENT-MAJOR in global (prep kernel) so each thread
//   loads its 8 fragment regs per (j-tile,kb) with 2x LDG.128.
//   3 passes Whi*Shi + Whi*Slo + Wlo*Shi accumulated in fp32 regs.
// ============================================================

#define THREADS 512
#define SB 16
#define BROW 240              // bytes per state row (112*2 = 224 + 16 pad)
#define BHALF (256 * BROW)    // 61440 per half

#define SM_BHI 0
#define SM_BLO BHALF
#define SM_W4   (2 * BHALF)         // 122880 : w4t[o][i] f32, 2048 B
#define SM_BIAS (SM_W4 + 2048)      // 124928 : b1,b2,b3 f32, 3072 B
#define SM_TOTAL (SM_BIAS + 3072)   // 128000
// final-layer fp32 state overlays BHI/BLO: S3f[c][i], row stride 1040 B
#define S3STRIDE 260                // floats per row (256 + 4 pad)

// fragment-major weight images: [L][jt(16)][kb(8)][lane(32)][8 x u32]
__device__ uint32_t g_WfH[3 * 16 * 8 * 32 * 8];
__device__ uint32_t g_WfL[3 * 16 * 8 * 32 * 8];

__device__ __forceinline__ uint32_t smem_u32(const void* p) {
    uint32_t a;
    asm("{ .reg .u64 t; cvta.to.shared.u64 t, %1; cvt.u32.u64 %0, t; }"
        : "=r"(a) : "l"(p));
    return a;
}
__device__ __forceinline__ void ldmB4(uint32_t* b, uint32_t addr) {
    asm volatile("ldmatrix.sync.aligned.m8n8.x4.trans.shared.b16 {%0,%1,%2,%3}, [%4];"
                 : "=r"(b[0]), "=r"(b[1]), "=r"(b[2]), "=r"(b[3]) : "r"(addr));
}
__device__ __forceinline__ void mma4(float* d, uint4 a, uint32_t b0, uint32_t b1) {
    asm volatile(
        "mma.sync.aligned.m16n8k16.row.col.f32.bf16.bf16.f32 "
        "{%0,%1,%2,%3}, {%4,%5,%6,%7}, {%8,%9}, {%0,%1,%2,%3};"
        : "+f"(d[0]), "+f"(d[1]), "+f"(d[2]), "+f"(d[3])
        : "r"(a.x), "r"(a.y), "r"(a.z), "r"(a.w), "r"(b0), "r"(b1));
}
__device__ __forceinline__ uint32_t pk2(float a, float b) {
    return (uint32_t)__bfloat16_as_ushort(__float2bfloat16(a)) |
           ((uint32_t)__bfloat16_as_ushort(__float2bfloat16(b)) << 16);
}

// ---------------- prep: W[L] (i-major) -> fragment-major hi/lo ----------
// out u32 index: (((L*16+jt)*8+kb)*32+lane)*8 + r
//   lane=(g,tg): g=lane>>2, tg=lane&3 ; r: kk=r>>2, rr=r&3
//   j = jt*16 + g + 8*(rr&1) ; i = kb*32 + kk*16 + 8*(rr>>1) + 2*tg
//   value = pack( bf16(W[i][j]), bf16(W[i+1][j]) )
__global__ void __launch_bounds__(256) prep_kernel(
    const float* __restrict__ W1, const float* __restrict__ W2,
    const float* __restrict__ W3)
{
    int idx = blockIdx.x * 256 + threadIdx.x;   // 0 .. 98303
    int L = idx / 32768;
    int rem = idx & 32767;
    int jt = rem >> 11;
    int kb = (rem >> 8) & 7;
    int lane = (rem >> 3) & 31;
    int r = rem & 7;
    int g = lane >> 2, tg = lane & 3;
    int kk = r >> 2, rr = r & 3;
    int j = jt * 16 + g + 8 * (rr & 1);
    int i = kb * 32 + kk * 16 + 8 * (rr >> 1) + 2 * tg;
    const float* W = (L == 0) ? W1 : ((L == 1) ? W2 : W3);
    float v0 = W[i * 256 + j];
    float v1 = W[(i + 1) * 256 + j];
    float h0 = __bfloat162float(__float2bfloat16(v0));
    float h1 = __bfloat162float(__float2bfloat16(v1));
    g_WfH[idx] = pk2(v0, v1);
    g_WfL[idx] = pk2(v0 - h0, v1 - h1);
}

// ---------------- main kernel ----------------
__global__ void __launch_bounds__(THREADS, 1) pinn_mma_kernel(
    const float* __restrict__ x,
    const float* __restrict__ W0, const float* __restrict__ b0_,
    const float* __restrict__ b1_, const float* __restrict__ b2_,
    const float* __restrict__ b3_,
    const float* __restrict__ W4, const float* __restrict__ b4,
    const float* __restrict__ lb, const float* __restrict__ ub,
    float* __restrict__ out, int N)
{
    extern __shared__ char sm[];
    const uint32_t smb = smem_u32(sm);
    const int tid  = threadIdx.x;
    const int warp = tid >> 5, lane = tid & 31;
    const int g = lane >> 2, tg = lane & 3;
    const int h  = warp & 1;             // ct parity = sample half
    const int wp = warp >> 1;            // j-tile pair index (0..7)
    const int s0 = blockIdx.x * SB;

    // stage W4 transposed (w4t[o][i]) and hidden biases
    ((float*)(sm + SM_W4))[(tid & 1) * 256 + (tid >> 1)] = W4[tid];
    if (tid < 256) {
        ((float*)(sm + SM_BIAS))[tid]       = b1_[tid];
        ((float*)(sm + SM_BIAS))[256 + tid] = b2_[tid];
        ((float*)(sm + SM_BIAS))[512 + tid] = b3_[tid];
    }

    // ---------- layer 0: 3 -> 256 (SIMT), write bf16 hi/lo state ----------
    {
        float lbv[3], sk[3];
#pragma unroll
        for (int k = 0; k < 3; k++) { lbv[k] = lb[k]; sk[k] = 2.0f / (ub[k] - lb[k]); }
        const int j = tid & 255;
        const int hh = tid >> 8;         // sample-half split across 512 threads
        float w[3];
#pragma unroll
        for (int k = 0; k < 3; k++) w[k] = W0[k * 256 + j];
        const float bj = b0_[j];
        float zj[3], Szl = 0.0f;
#pragma unroll
        for (int k = 0; k < 3; k++) { zj[k] = w[k] * sk[k]; Szl += zj[k]; }
#pragma unroll
        for (int spp = 0; spp < 4; spp++) {
            const int sp = hh * 4 + spp;
            float v[2][7];
#pragma unroll
            for (int p = 0; p < 2; p++) {
                const int s = 2 * sp + p;
                float xn0 = sk[0] * (x[(s0 + s) * 3 + 0] - lbv[0]) - 1.0f;
                float xn1 = sk[1] * (x[(s0 + s) * 3 + 1] - lbv[1]) - 1.0f;
                float xn2 = sk[2] * (x[(s0 + s) * 3 + 2] - lbv[2]) - 1.0f;
                float z = bj + w[0] * xn0 + w[1] * xn1 + w[2] * xn2;
                float t = tanhf(z);
                float gg = 1.0f - t * t;
                float u = -2.0f * t * gg * Szl;
                v[p][0] = t;
#pragma unroll
                for (int k = 0; k < 3; k++) { v[p][1 + k] = gg * zj[k]; v[p][4 + k] = u * zj[k]; }
            }
#pragma unroll
            for (int q = 0; q < 7; q++) {
                const int off = j * BROW + 32 * q + 4 * sp;   // col = 16q + 2sp
                float h0 = __bfloat162float(__float2bfloat16(v[0][q]));
                float h1 = __bfloat162float(__float2bfloat16(v[1][q]));
                *(uint32_t*)(sm + SM_BHI + off) = pk2(v[0][q], v[1][q]);
                *(uint32_t*)(sm + SM_BLO + off) = pk2(v[0][q] - h0, v[1][q] - h1);
            }
        }
    }
    __syncthreads();

    // ---------- hidden layers 1..3 via mma.sync ----------
#pragma unroll 1
    for (int L = 0; L < 3; L++) {
        float acc[2][7][4];                  // [j-tile][quantity][frag]
#pragma unroll
        for (int jj = 0; jj < 2; jj++)
#pragma unroll
            for (int q = 0; q < 7; q++)
#pragma unroll
                for (int d = 0; d < 4; d++) acc[jj][q][d] = 0.0f;

#pragma unroll 1
        for (int kb = 0; kb < 8; kb++) {
            // fragment-major A: 2x LDG.128 per (jj, hi/lo)
            uint4 ah0[2], ah1[2], al0[2], al1[2];
#pragma unroll
            for (int jj = 0; jj < 2; jj++) {
                const int base =
                    (((L * 16 + (wp * 2 + jj)) * 8 + kb) * 32 + lane) * 2;
                const uint4* FH = reinterpret_cast<const uint4*>(g_WfH);
                const uint4* FL = reinterpret_cast<const uint4*>(g_WfL);
                ah0[jj] = FH[base];
                ah1[jj] = FH[base + 1];
                al0[jj] = FL[base];
                al1[jj] = FL[base + 1];
            }
#pragma unroll
            for (int q = 0; q < 7; q++) {
                const int ct = 2 * q + h;
                const uint32_t baddr = smb + SM_BHI +
                    (uint32_t)(kb * 32 * BROW) + (uint32_t)(lane * BROW) + ct * 16;
                uint32_t bh[4], bl[4];
                ldmB4(bh, baddr);
                ldmB4(bl, baddr + BHALF);
                // interleave the two accumulator chains (jj=0/1)
                mma4(acc[0][q], ah0[0], bh[0], bh[1]);
                mma4(acc[1][q], ah0[1], bh[0], bh[1]);
                mma4(acc[0][q], ah1[0], bh[2], bh[3]);
                mma4(acc[1][q], ah1[1], bh[2], bh[3]);
                mma4(acc[0][q], ah0[0], bl[0], bl[1]);
                mma4(acc[1][q], ah0[1], bl[0], bl[1]);
                mma4(acc[0][q], ah1[0], bl[2], bl[3]);
                mma4(acc[1][q], ah1[1], bl[2], bl[3]);
                mma4(acc[0][q], al0[0], bh[0], bh[1]);
                mma4(acc[1][q], al0[1], bh[0], bh[1]);
                mma4(acc[0][q], al1[0], bh[2], bh[3]);
                mma4(acc[1][q], al1[1], bh[2], bh[3]);
            }
        }
        __syncthreads();   // all reads of old state done

        // ---------- elementwise (thread-local) ----------
        const float* bias = (const float*)(sm + SM_BIAS) + L * 256;
        const bool last = (L == 2);
        const int se = 8 * h + 2 * tg;       // even sample index owned by this thread
#pragma unroll
        for (int jj = 0; jj < 2; jj++) {
#pragma unroll
            for (int r = 0; r < 2; r++) {
                const int j = (wp * 2 + jj) * 16 + g + 8 * r;
                const float bj = bias[j];
                float v[2][7];
#pragma unroll
                for (int p = 0; p < 2; p++) {
                    const int d = 2 * r + p;
                    float zh = acc[jj][0][d] + bj;
                    float z0 = acc[jj][1][d];
                    float z1 = acc[jj][2][d];
                    float z2 = acc[jj][3][d];
                    float t0 = acc[jj][4][d];
                    float t1 = acc[jj][5][d];
                    float t2 = acc[jj][6][d];
                    float t = tanhf(zh);
                    float gg = 1.0f - t * t;
                    float Sz = z0 + z1 + z2;
                    float u = -2.0f * t * gg * Sz;
                    v[p][0] = t;
                    v[p][1] = gg * z0; v[p][2] = gg * z1; v[p][3] = gg * z2;
                    v[p][4] = u * z0 + gg * t0;
                    v[p][5] = u * z1 + gg * t1;
                    v[p][6] = u * z2 + gg * t2;
                }
                if (!last) {
#pragma unroll
                    for (int q = 0; q < 7; q++) {
                        const int off = j * BROW + (16 * q + se) * 2;
                        float h0 = __bfloat162float(__float2bfloat16(v[0][q]));
                        float h1 = __bfloat162float(__float2bfloat16(v[1][q]));
                        *(uint32_t*)(sm + SM_BHI + off) = pk2(v[0][q], v[1][q]);
                        *(uint32_t*)(sm + SM_BLO + off) = pk2(v[0][q] - h0, v[1][q] - h1);
                    }
                } else {
#pragma unroll
                    for (int q = 0; q < 7; q++) {
                        ((float*)sm)[(16 * q + se) * S3STRIDE + j]     = v[0][q];
                        ((float*)sm)[(16 * q + se + 1) * S3STRIDE + j] = v[1][q];
                    }
                }
            }
        }
        __syncthreads();
    }

    // ---------- final layer: 256 -> 2 ----------
    if (tid < 224) {
        const int o = tid & 1, c = tid >> 1;
        const float4* row = reinterpret_cast<const float4*>(sm + (size_t)c * (S3STRIDE * 4));
        const float4* wr  = reinterpret_cast<const float4*>(sm + SM_W4 + o * 1024);
        float sum = 0.0f;
#pragma unroll 8
        for (int i4 = 0; i4 < 64; i4++) {
            float4 a = row[i4];
            float4 b = wr[i4];
            sum += a.x * b.x + a.y * b.y + a.z * b.z + a.w * b.w;
        }
        const int q = c >> 4, s = c & 15;
        const int n = s0 + s;
        if (q == 0) {
            out[n * 2 + o] = sum + b4[o];
        } else if (q < 4) {
            out[2 * N + o * 3 * N + n * 3 + (q - 1)] = sum;
        } else {
            out[8 * N + o * 3 * N + n * 3 + (q - 4)] = sum;
        }
    }
}

extern "C" void kernel_launch(void* const* d_in, const int* in_sizes, int n_in,
                              void* d_out, int out_size)
{
    const float* x  = (const float*)d_in[0];
    const float* W0 = (const float*)d_in[1];
    const float* b0 = (const float*)d_in[2];
    const float* W1 = (const float*)d_in[3];
    const float* b1 = (const float*)d_in[4];
    const float* W2 = (const float*)d_in[5];
    const float* b2 = (const float*)d_in[6];
    const float* W3 = (const float*)d_in[7];
    const float* b3 = (const float*)d_in[8];
    const float* W4 = (const float*)d_in[9];
    const float* b4 = (const float*)d_in[10];
    const float* lb = (const float*)d_in[11];
    const float* ub = (const float*)d_in[12];
    float* out = (float*)d_out;

    const int N = in_sizes[0] / 3;          // 32768

    prep_kernel<<<3 * 32768 / 256, 256>>>(W1, W2, W3);

    cudaFuncSetAttribute(pinn_mma_kernel,
                         cudaFuncAttributeMaxDynamicSharedMemorySize, SM_TOTAL);
    pinn_mma_kernel<<<N / SB, THREADS, SM_TOTAL>>>(
        x, W0, b0, b1, b2, b3, W4, b4, lb, ub, out, N);
}

// round 13
// speedup vs baseline: 2.2886x; 1.4375x over previous
#include <cuda_runtime.h>
#include <cuda_fp16.h>
#include <cstdint>

// ============================================================
// PINN fwd + 1st/2nd derivatives via mma.sync (HMMA) fp16 2-pass
//   CTA: 16 samples, 512 threads / 16 warps.
//   Warp w: j-tile pair wp=w>>1 (32 M-rows) x ct-parity h=w&1.
//   State S single fp16, double-buffered. W = Whi + Wlo (fp16 each).
//   Layer GEMM: D = Whi*S + Wlo*S, fp32 accum -> per-term err ~2^-11.
//   One ldmatrix.x4 feeds 8 MMAs. One barrier per layer.
// ============================================================

#define THREADS 512
#define SB 16
#define BROW 240              // bytes per state row (112*2 = 224 + 16 pad)
#define BUFSZ (256 * BROW)    // 61440 per buffer

#define SM_B0 0
#define SM_B1 BUFSZ
#define SM_W4   (2 * BUFSZ)         // 122880 : w4t[o][i] f32, 2048 B
#define SM_BIAS (SM_W4 + 2048)      // 124928 : b1,b2,b3 f32, 3072 B
#define SM_TOTAL (SM_BIAS + 3072)   // 128000
// final-layer fp32 state overlays both buffers: S3f[c][i], stride 1040 B
#define S3STRIDE 260                // floats per row (256 + 4 pad)

// fragment-major weight images: [L][jt(16)][kb(8)][lane(32)][8 x u32] fp16x2
__device__ uint32_t g_WfH[3 * 16 * 8 * 32 * 8];
__device__ uint32_t g_WfL[3 * 16 * 8 * 32 * 8];

__device__ __forceinline__ uint32_t smem_u32(const void* p) {
    uint32_t a;
    asm("{ .reg .u64 t; cvta.to.shared.u64 t, %1; cvt.u32.u64 %0, t; }"
        : "=r"(a) : "l"(p));
    return a;
}
__device__ __forceinline__ void ldmB4(uint32_t* b, uint32_t addr) {
    asm volatile("ldmatrix.sync.aligned.m8n8.x4.trans.shared.b16 {%0,%1,%2,%3}, [%4];"
                 : "=r"(b[0]), "=r"(b[1]), "=r"(b[2]), "=r"(b[3]) : "r"(addr));
}
__device__ __forceinline__ void mma4(float* d, uint4 a, uint32_t b0, uint32_t b1) {
    asm volatile(
        "mma.sync.aligned.m16n8k16.row.col.f32.f16.f16.f32 "
        "{%0,%1,%2,%3}, {%4,%5,%6,%7}, {%8,%9}, {%0,%1,%2,%3};"
        : "+f"(d[0]), "+f"(d[1]), "+f"(d[2]), "+f"(d[3])
        : "r"(a.x), "r"(a.y), "r"(a.z), "r"(a.w), "r"(b0), "r"(b1));
}
__device__ __forceinline__ uint32_t pk2h(float a, float b) {
    __half2 h = __float22half2_rn(make_float2(a, b));
    return *reinterpret_cast<uint32_t*>(&h);
}

// ---------------- prep: W[L] (i-major) -> fragment-major fp16 hi/lo ------
// out u32 index: (((L*16+jt)*8+kb)*32+lane)*8 + r
//   lane=(g,tg): g=lane>>2, tg=lane&3 ; r: kk=r>>2, rr=r&3
//   j = jt*16 + g + 8*(rr&1) ; i = kb*32 + kk*16 + 8*(rr>>1) + 2*tg
//   value = pack( fp16(W[i][j]), fp16(W[i+1][j]) ), lo = residual
__global__ void __launch_bounds__(256) prep_kernel(
    const float* __restrict__ W1, const float* __restrict__ W2,
    const float* __restrict__ W3)
{
    int idx = blockIdx.x * 256 + threadIdx.x;   // 0 .. 98303
    int L = idx / 32768;
    int rem = idx & 32767;
    int jt = rem >> 11;
    int kb = (rem >> 8) & 7;
    int lane = (rem >> 3) & 31;
    int r = rem & 7;
    int g = lane >> 2, tg = lane & 3;
    int kk = r >> 2, rr = r & 3;
    int j = jt * 16 + g + 8 * (rr & 1);
    int i = kb * 32 + kk * 16 + 8 * (rr >> 1) + 2 * tg;
    const float* W = (L == 0) ? W1 : ((L == 1) ? W2 : W3);
    float v0 = W[i * 256 + j];
    float v1 = W[(i + 1) * 256 + j];
    float h0 = __half2float(__float2half_rn(v0));
    float h1 = __half2float(__float2half_rn(v1));
    g_WfH[idx] = pk2h(v0, v1);
    g_WfL[idx] = pk2h(v0 - h0, v1 - h1);
}

// ---------------- main kernel ----------------
__global__ void __launch_bounds__(THREADS, 1) pinn_mma_kernel(
    const float* __restrict__ x,
    const float* __restrict__ W0, const float* __restrict__ b0_,
    const float* __restrict__ b1_, const float* __restrict__ b2_,
    const float* __restrict__ b3_,
    const float* __restrict__ W4, const float* __restrict__ b4,
    const float* __restrict__ lb, const float* __restrict__ ub,
    float* __restrict__ out, int N)
{
    extern __shared__ char sm[];
    const uint32_t smb = smem_u32(sm);
    const int tid  = threadIdx.x;
    const int warp = tid >> 5, lane = tid & 31;
    const int g = lane >> 2, tg = lane & 3;
    const int h  = warp & 1;             // ct parity = sample half
    const int wp = warp >> 1;            // j-tile pair index (0..7)
    const int s0 = blockIdx.x * SB;

    // stage W4 transposed (w4t[o][i]) and hidden biases
    ((float*)(sm + SM_W4))[(tid & 1) * 256 + (tid >> 1)] = W4[tid];
    if (tid < 256) {
        ((float*)(sm + SM_BIAS))[tid]       = b1_[tid];
        ((float*)(sm + SM_BIAS))[256 + tid] = b2_[tid];
        ((float*)(sm + SM_BIAS))[512 + tid] = b3_[tid];
    }

    // ---------- layer 0: 3 -> 256 (SIMT), write fp16 state to buf0 -------
    {
        float lbv[3], sk[3];
#pragma unroll
        for (int k = 0; k < 3; k++) { lbv[k] = lb[k]; sk[k] = 2.0f / (ub[k] - lb[k]); }
        const int j = tid & 255;
        const int hh = tid >> 8;         // sample-half split across 512 threads
        float w[3];
#pragma unroll
        for (int k = 0; k < 3; k++) w[k] = W0[k * 256 + j];
        const float bj = b0_[j];
        float zj[3], Szl = 0.0f;
#pragma unroll
        for (int k = 0; k < 3; k++) { zj[k] = w[k] * sk[k]; Szl += zj[k]; }
#pragma unroll
        for (int spp = 0; spp < 4; spp++) {
            const int sp = hh * 4 + spp;
            float v[2][7];
#pragma unroll
            for (int p = 0; p < 2; p++) {
                const int s = 2 * sp + p;
                float xn0 = sk[0] * (x[(s0 + s) * 3 + 0] - lbv[0]) - 1.0f;
                float xn1 = sk[1] * (x[(s0 + s) * 3 + 1] - lbv[1]) - 1.0f;
                float xn2 = sk[2] * (x[(s0 + s) * 3 + 2] - lbv[2]) - 1.0f;
                float z = bj + w[0] * xn0 + w[1] * xn1 + w[2] * xn2;
                float t = tanhf(z);
                float gg = 1.0f - t * t;
                float u = -2.0f * t * gg * Szl;
                v[p][0] = t;
#pragma unroll
                for (int k = 0; k < 3; k++) { v[p][1 + k] = gg * zj[k]; v[p][4 + k] = u * zj[k]; }
            }
#pragma unroll
            for (int q = 0; q < 7; q++) {
                const int off = j * BROW + 32 * q + 4 * sp;   // col = 16q + 2sp
                *(uint32_t*)(sm + SM_B0 + off) = pk2h(v[0][q], v[1][q]);
            }
        }
    }
    __syncthreads();

    // ---------- hidden layers 1..3 via mma.sync (2-pass fp16) ----------
#pragma unroll 1
    for (int L = 0; L < 3; L++) {
        const uint32_t bufR = smb + ((L == 1) ? SM_B1 : SM_B0);
        const uint32_t bufW = smb + ((L == 0) ? SM_B1 : SM_B0);

        float acc[2][7][4];                  // [j-tile][quantity][frag]
#pragma unroll
        for (int jj = 0; jj < 2; jj++)
#pragma unroll
            for (int q = 0; q < 7; q++)
#pragma unroll
                for (int d = 0; d < 4; d++) acc[jj][q][d] = 0.0f;

#pragma unroll 1
        for (int kb = 0; kb < 8; kb++) {
            // fragment-major A: 2x LDG.128 per (jj, hi/lo)
            uint4 ah0[2], ah1[2], al0[2], al1[2];
#pragma unroll
            for (int jj = 0; jj < 2; jj++) {
                const int base =
                    (((L * 16 + (wp * 2 + jj)) * 8 + kb) * 32 + lane) * 2;
                const uint4* FH = reinterpret_cast<const uint4*>(g_WfH);
                const uint4* FL = reinterpret_cast<const uint4*>(g_WfL);
                ah0[jj] = FH[base];
                ah1[jj] = FH[base + 1];
                al0[jj] = FL[base];
                al1[jj] = FL[base + 1];
            }
#pragma unroll
            for (int q = 0; q < 7; q++) {
                const int ct = 2 * q + h;
                const uint32_t baddr = bufR +
                    (uint32_t)(kb * 32 * BROW) + (uint32_t)(lane * BROW) + ct * 16;
                uint32_t b[4];
                ldmB4(b, baddr);
                // interleave the two accumulator chains (jj=0/1)
                mma4(acc[0][q], ah0[0], b[0], b[1]);
                mma4(acc[1][q], ah0[1], b[0], b[1]);
                mma4(acc[0][q], ah1[0], b[2], b[3]);
                mma4(acc[1][q], ah1[1], b[2], b[3]);
                mma4(acc[0][q], al0[0], b[0], b[1]);
                mma4(acc[1][q], al0[1], b[0], b[1]);
                mma4(acc[0][q], al1[0], b[2], b[3]);
                mma4(acc[1][q], al1[1], b[2], b[3]);
            }
        }

        const bool last = (L == 2);
        if (last) __syncthreads();   // S3f overlays buffers; all reads must drain

        // ---------- elementwise (thread-local; writes bufW != bufR) ------
        const float* bias = (const float*)(sm + SM_BIAS) + L * 256;
        const int se = 8 * h + 2 * tg;       // even sample index owned by this thread
#pragma unroll
        for (int jj = 0; jj < 2; jj++) {
#pragma unroll
            for (int r = 0; r < 2; r++) {
                const int j = (wp * 2 + jj) * 16 + g + 8 * r;
                const float bj = bias[j];
                float v[2][7];
#pragma unroll
                for (int p = 0; p < 2; p++) {
                    const int d = 2 * r + p;
                    float zh = acc[jj][0][d] + bj;
                    float z0 = acc[jj][1][d];
                    float z1 = acc[jj][2][d];
                    float z2 = acc[jj][3][d];
                    float t0 = acc[jj][4][d];
                    float t1 = acc[jj][5][d];
                    float t2 = acc[jj][6][d];
                    float t = tanhf(zh);
                    float gg = 1.0f - t * t;
                    float Sz = z0 + z1 + z2;
                    float u = -2.0f * t * gg * Sz;
                    v[p][0] = t;
                    v[p][1] = gg * z0; v[p][2] = gg * z1; v[p][3] = gg * z2;
                    v[p][4] = u * z0 + gg * t0;
                    v[p][5] = u * z1 + gg * t1;
                    v[p][6] = u * z2 + gg * t2;
                }
                if (!last) {
#pragma unroll
                    for (int q = 0; q < 7; q++) {
                        const int off = j * BROW + (16 * q + se) * 2;
                        *(uint32_t*)(bufW - smb + sm + off) = pk2h(v[0][q], v[1][q]);
                    }
                } else {
#pragma unroll
                    for (int q = 0; q < 7; q++) {
                        ((float*)sm)[(16 * q + se) * S3STRIDE + j]     = v[0][q];
                        ((float*)sm)[(16 * q + se + 1) * S3STRIDE + j] = v[1][q];
                    }
                }
            }
        }
        __syncthreads();
    }

    // ---------- final layer: 256 -> 2 ----------
    if (tid < 224) {
        const int o = tid & 1, c = tid >> 1;
        const float4* row = reinterpret_cast<const float4*>(sm + (size_t)c * (S3STRIDE * 4));
        const float4* wr  = reinterpret_cast<const float4*>(sm + SM_W4 + o * 1024);
        float sum = 0.0f;
#pragma unroll 8
        for (int i4 = 0; i4 < 64; i4++) {
            float4 a = row[i4];
            float4 b = wr[i4];
            sum += a.x * b.x + a.y * b.y + a.z * b.z + a.w * b.w;
        }
        const int q = c >> 4, s = c & 15;
        const int n = s0 + s;
        if (q == 0) {
            out[n * 2 + o] = sum + b4[o];
        } else if (q < 4) {
            out[2 * N + o * 3 * N + n * 3 + (q - 1)] = sum;
        } else {
            out[8 * N + o * 3 * N + n * 3 + (q - 4)] = sum;
        }
    }
}

extern "C" void kernel_launch(void* const* d_in, const int* in_sizes, int n_in,
                              void* d_out, int out_size)
{
    const float* x  = (const float*)d_in[0];
    const float* W0 = (const float*)d_in[1];
    const float* b0 = (const float*)d_in[2];
    const float* W1 = (const float*)d_in[3];
    const float* b1 = (const float*)d_in[4];
    const float* W2 = (const float*)d_in[5];
    const float* b2 = (const float*)d_in[6];
    const float* W3 = (const float*)d_in[7];
    const float* b3 = (const float*)d_in[8];
    const float* W4 = (const float*)d_in[9];
    const float* b4 = (const float*)d_in[10];
    const float* lb = (const float*)d_in[11];
    const float* ub = (const float*)d_in[12];
    float* out = (float*)d_out;

    const int N = in_sizes[0] / 3;          // 32768

    prep_kernel<<<3 * 32768 / 256, 256>>>(W1, W2, W3);

    cudaFuncSetAttribute(pinn_mma_kernel,
                         cudaFuncAttributeMaxDynamicSharedMemorySize, SM_TOTAL);
    pinn_mma_kernel<<<N / SB, THREADS, SM_TOTAL>>>(
        x, W0, b0, b1, b2, b3, W4, b4, lb, ub, out, N);
}

// round 14
// speedup vs baseline: 2.3561x; 1.0295x over previous
#include <cuda_runtime.h>
#include <cuda_fp16.h>
#include <cstdint>

// ============================================================
// PINN fwd + 1st/2nd derivatives via mma.sync (HMMA) fp16 2-pass
//   CTA: 16 samples, 512 threads / 16 warps.
//   Warp w: j-tile pair wp=w>>1 (32 M-rows) x ct-parity h=w&1.
//   State S single fp16, double-buffered. W = Whi + Wlo (fp16 each).
//   Layer GEMM: D = Whi*S + Wlo*S, fp32 accum.
//   Pass-major MMA issue order: all 14 accumulators swept per pass ->
//   dependent-chain reuse distance 14 (covers HMMA latency in-warp).
// ============================================================

#define THREADS 512
#define SB 16
#define BROW 240              // bytes per state row (112*2 = 224 + 16 pad)
#define BUFSZ (256 * BROW)    // 61440 per buffer

#define SM_B0 0
#define SM_B1 BUFSZ
#define SM_W4   (2 * BUFSZ)         // 122880 : w4t[o][i] f32, 2048 B
#define SM_BIAS (SM_W4 + 2048)      // 124928 : b1,b2,b3 f32, 3072 B
#define SM_TOTAL (SM_BIAS + 3072)   // 128000
// final-layer fp32 state overlays both buffers: S3f[c][i], stride 1040 B
#define S3STRIDE 260                // floats per row (256 + 4 pad)

// fragment-major weight images: [L][jt(16)][kb(8)][lane(32)][8 x u32] fp16x2
__device__ uint32_t g_WfH[3 * 16 * 8 * 32 * 8];
__device__ uint32_t g_WfL[3 * 16 * 8 * 32 * 8];

__device__ __forceinline__ uint32_t smem_u32(const void* p) {
    uint32_t a;
    asm("{ .reg .u64 t; cvta.to.shared.u64 t, %1; cvt.u32.u64 %0, t; }"
        : "=r"(a) : "l"(p));
    return a;
}
__device__ __forceinline__ void ldmB4(uint32_t* b, uint32_t addr) {
    asm volatile("ldmatrix.sync.aligned.m8n8.x4.trans.shared.b16 {%0,%1,%2,%3}, [%4];"
                 : "=r"(b[0]), "=r"(b[1]), "=r"(b[2]), "=r"(b[3]) : "r"(addr));
}
__device__ __forceinline__ void mma4(float* d, uint4 a, uint32_t b0, uint32_t b1) {
    asm volatile(
        "mma.sync.aligned.m16n8k16.row.col.f32.f16.f16.f32 "
        "{%0,%1,%2,%3}, {%4,%5,%6,%7}, {%8,%9}, {%0,%1,%2,%3};"
        : "+f"(d[0]), "+f"(d[1]), "+f"(d[2]), "+f"(d[3])
        : "r"(a.x), "r"(a.y), "r"(a.z), "r"(a.w), "r"(b0), "r"(b1));
}
__device__ __forceinline__ uint32_t pk2h(float a, float b) {
    __half2 h = __float22half2_rn(make_float2(a, b));
    return *reinterpret_cast<uint32_t*>(&h);
}

// ---------------- prep: W[L] (i-major) -> fragment-major fp16 hi/lo ------
__global__ void __launch_bounds__(256) prep_kernel(
    const float* __restrict__ W1, const float* __restrict__ W2,
    const float* __restrict__ W3)
{
    int idx = blockIdx.x * 256 + threadIdx.x;   // 0 .. 98303
    int L = idx / 32768;
    int rem = idx & 32767;
    int jt = rem >> 11;
    int kb = (rem >> 8) & 7;
    int lane = (rem >> 3) & 31;
    int r = rem & 7;
    int g = lane >> 2, tg = lane & 3;
    int kk = r >> 2, rr = r & 3;
    int j = jt * 16 + g + 8 * (rr & 1);
    int i = kb * 32 + kk * 16 + 8 * (rr >> 1) + 2 * tg;
    const float* W = (L == 0) ? W1 : ((L == 1) ? W2 : W3);
    float v0 = W[i * 256 + j];
    float v1 = W[(i + 1) * 256 + j];
    float h0 = __half2float(__float2half_rn(v0));
    float h1 = __half2float(__float2half_rn(v1));
    g_WfH[idx] = pk2h(v0, v1);
    g_WfL[idx] = pk2h(v0 - h0, v1 - h1);
}

// ---------------- main kernel ----------------
__global__ void __launch_bounds__(THREADS, 1) pinn_mma_kernel(
    const float* __restrict__ x,
    const float* __restrict__ W0, const float* __restrict__ b0_,
    const float* __restrict__ b1_, const float* __restrict__ b2_,
    const float* __restrict__ b3_,
    const float* __restrict__ W4, const float* __restrict__ b4,
    const float* __restrict__ lb, const float* __restrict__ ub,
    float* __restrict__ out, int N)
{
    extern __shared__ char sm[];
    const uint32_t smb = smem_u32(sm);
    const int tid  = threadIdx.x;
    const int warp = tid >> 5, lane = tid & 31;
    const int g = lane >> 2, tg = lane & 3;
    const int h  = warp & 1;             // ct parity = sample half
    const int wp = warp >> 1;            // j-tile pair index (0..7)
    const int s0 = blockIdx.x * SB;

    // stage W4 transposed (w4t[o][i]) and hidden biases
    ((float*)(sm + SM_W4))[(tid & 1) * 256 + (tid >> 1)] = W4[tid];
    if (tid < 256) {
        ((float*)(sm + SM_BIAS))[tid]       = b1_[tid];
        ((float*)(sm + SM_BIAS))[256 + tid] = b2_[tid];
        ((float*)(sm + SM_BIAS))[512 + tid] = b3_[tid];
    }

    // ---------- layer 0: 3 -> 256 (SIMT), write fp16 state to buf0 -------
    {
        float lbv[3], sk[3];
#pragma unroll
        for (int k = 0; k < 3; k++) { lbv[k] = lb[k]; sk[k] = 2.0f / (ub[k] - lb[k]); }
        const int j = tid & 255;
        const int hh = tid >> 8;         // sample-half split across 512 threads
        float w[3];
#pragma unroll
        for (int k = 0; k < 3; k++) w[k] = W0[k * 256 + j];
        const float bj = b0_[j];
        float zj[3], Szl = 0.0f;
#pragma unroll
        for (int k = 0; k < 3; k++) { zj[k] = w[k] * sk[k]; Szl += zj[k]; }
#pragma unroll
        for (int spp = 0; spp < 4; spp++) {
            const int sp = hh * 4 + spp;
            float v[2][7];
#pragma unroll
            for (int p = 0; p < 2; p++) {
                const int s = 2 * sp + p;
                float xn0 = sk[0] * (x[(s0 + s) * 3 + 0] - lbv[0]) - 1.0f;
                float xn1 = sk[1] * (x[(s0 + s) * 3 + 1] - lbv[1]) - 1.0f;
                float xn2 = sk[2] * (x[(s0 + s) * 3 + 2] - lbv[2]) - 1.0f;
                float z = bj + w[0] * xn0 + w[1] * xn1 + w[2] * xn2;
                float t = tanhf(z);
                float gg = 1.0f - t * t;
                float u = -2.0f * t * gg * Szl;
                v[p][0] = t;
#pragma unroll
                for (int k = 0; k < 3; k++) { v[p][1 + k] = gg * zj[k]; v[p][4 + k] = u * zj[k]; }
            }
#pragma unroll
            for (int q = 0; q < 7; q++) {
                const int off = j * BROW + 32 * q + 4 * sp;   // col = 16q + 2sp
                *(uint32_t*)(sm + SM_B0 + off) = pk2h(v[0][q], v[1][q]);
            }
        }
    }
    __syncthreads();

    // ---------- hidden layers 1..3 via mma.sync (2-pass fp16) ----------
#pragma unroll 1
    for (int L = 0; L < 3; L++) {
        const uint32_t bufR = smb + ((L == 1) ? SM_B1 : SM_B0);
        const uint32_t bufW = smb + ((L == 0) ? SM_B1 : SM_B0);

        float acc[2][7][4];                  // [j-tile][quantity][frag]
#pragma unroll
        for (int jj = 0; jj < 2; jj++)
#pragma unroll
            for (int q = 0; q < 7; q++)
#pragma unroll
                for (int d = 0; d < 4; d++) acc[jj][q][d] = 0.0f;

#pragma unroll 1
        for (int kb = 0; kb < 8; kb++) {
            // fragment-major A: 2x LDG.128 per (jj, hi/lo)
            uint4 ah0[2], ah1[2], al0[2], al1[2];
#pragma unroll
            for (int jj = 0; jj < 2; jj++) {
                const int base =
                    (((L * 16 + (wp * 2 + jj)) * 8 + kb) * 32 + lane) * 2;
                const uint4* FH = reinterpret_cast<const uint4*>(g_WfH);
                const uint4* FL = reinterpret_cast<const uint4*>(g_WfL);
                ah0[jj] = FH[base];
                ah1[jj] = FH[base + 1];
                al0[jj] = FL[base];
                al1[jj] = FL[base + 1];
            }
            // all 7 B fragments for this kb up front (28 regs)
            uint32_t b[7][4];
#pragma unroll
            for (int q = 0; q < 7; q++) {
                const int ct = 2 * q + h;
                const uint32_t baddr = bufR +
                    (uint32_t)(kb * 32 * BROW) + (uint32_t)(lane * BROW) + ct * 16;
                ldmB4(b[q], baddr);
            }
            // pass-major issue: dependent reuse distance = 14 MMAs
#pragma unroll
            for (int q = 0; q < 7; q++) {
                mma4(acc[0][q], ah0[0], b[q][0], b[q][1]);
                mma4(acc[1][q], ah0[1], b[q][0], b[q][1]);
            }
#pragma unroll
            for (int q = 0; q < 7; q++) {
                mma4(acc[0][q], ah1[0], b[q][2], b[q][3]);
                mma4(acc[1][q], ah1[1], b[q][2], b[q][3]);
            }
#pragma unroll
            for (int q = 0; q < 7; q++) {
                mma4(acc[0][q], al0[0], b[q][0], b[q][1]);
                mma4(acc[1][q], al0[1], b[q][0], b[q][1]);
            }
#pragma unroll
            for (int q = 0; q < 7; q++) {
                mma4(acc[0][q], al1[0], b[q][2], b[q][3]);
                mma4(acc[1][q], al1[1], b[q][2], b[q][3]);
            }
        }

        const bool last = (L == 2);
        if (last) __syncthreads();   // S3f overlays buffers; all reads must drain

        // ---------- elementwise (thread-local; writes bufW != bufR) ------
        const float* bias = (const float*)(sm + SM_BIAS) + L * 256;
        const int se = 8 * h + 2 * tg;       // even sample index owned by this thread
#pragma unroll
        for (int jj = 0; jj < 2; jj++) {
#pragma unroll
            for (int r = 0; r < 2; r++) {
                const int j = (wp * 2 + jj) * 16 + g + 8 * r;
                const float bj = bias[j];
                float v[2][7];
#pragma unroll
                for (int p = 0; p < 2; p++) {
                    const int d = 2 * r + p;
                    float zh = acc[jj][0][d] + bj;
                    float z0 = acc[jj][1][d];
                    float z1 = acc[jj][2][d];
                    float z2 = acc[jj][3][d];
                    float t0 = acc[jj][4][d];
                    float t1 = acc[jj][5][d];
                    float t2 = acc[jj][6][d];
                    float t = tanhf(zh);
                    float gg = 1.0f - t * t;
                    float Sz = z0 + z1 + z2;
                    float u = -2.0f * t * gg * Sz;
                    v[p][0] = t;
                    v[p][1] = gg * z0; v[p][2] = gg * z1; v[p][3] = gg * z2;
                    v[p][4] = u * z0 + gg * t0;
                    v[p][5] = u * z1 + gg * t1;
                    v[p][6] = u * z2 + gg * t2;
                }
                if (!last) {
#pragma unroll
                    for (int q = 0; q < 7; q++) {
                        const int off = j * BROW + (16 * q + se) * 2;
                        *(uint32_t*)(bufW - smb + sm + off) = pk2h(v[0][q], v[1][q]);
                    }
                } else {
#pragma unroll
                    for (int q = 0; q < 7; q++) {
                        ((float*)sm)[(16 * q + se) * S3STRIDE + j]     = v[0][q];
                        ((float*)sm)[(16 * q + se + 1) * S3STRIDE + j] = v[1][q];
                    }
                }
            }
        }
        __syncthreads();
    }

    // ---------- final layer: 256 -> 2 ----------
    if (tid < 224) {
        const int o = tid & 1, c = tid >> 1;
        const float4* row = reinterpret_cast<const float4*>(sm + (size_t)c * (S3STRIDE * 4));
        const float4* wr  = reinterpret_cast<const float4*>(sm + SM_W4 + o * 1024);
        float sum = 0.0f;
#pragma unroll 8
        for (int i4 = 0; i4 < 64; i4++) {
            float4 a = row[i4];
            float4 b = wr[i4];
            sum += a.x * b.x + a.y * b.y + a.z * b.z + a.w * b.w;
        }
        const int q = c >> 4, s = c & 15;
        const int n = s0 + s;
        if (q == 0) {
            out[n * 2 + o] = sum + b4[o];
        } else if (q < 4) {
            out[2 * N + o * 3 * N + n * 3 + (q - 1)] = sum;
        } else {
            out[8 * N + o * 3 * N + n * 3 + (q - 4)] = sum;
        }
    }
}

extern "C" void kernel_launch(void* const* d_in, const int* in_sizes, int n_in,
                              void* d_out, int out_size)
{
    const float* x  = (const float*)d_in[0];
    const float* W0 = (const float*)d_in[1];
    const float* b0 = (const float*)d_in[2];
    const float* W1 = (const float*)d_in[3];
    const float* b1 = (const float*)d_in[4];
    const float* W2 = (const float*)d_in[5];
    const float* b2 = (const float*)d_in[6];
    const float* W3 = (const float*)d_in[7];
    const float* b3 = (const float*)d_in[8];
    const float* W4 = (const float*)d_in[9];
    const float* b4 = (const float*)d_in[10];
    const float* lb = (const float*)d_in[11];
    const float* ub = (const float*)d_in[12];
    float* out = (float*)d_out;

    const int N = in_sizes[0] / 3;          // 32768

    prep_kernel<<<3 * 32768 / 256, 256>>>(W1, W2, W3);

    cudaFuncSetAttribute(pinn_mma_kernel,
                         cudaFuncAttributeMaxDynamicSharedMemorySize, SM_TOTAL);
    pinn_mma_kernel<<<N / SB, THREADS, SM_TOTAL>>>(
        x, W0, b0, b1, b2, b3, W4, b4, lb, ub, out, N);
}

// round 15
// speedup vs baseline: 2.5887x; 1.0988x over previous
#include <cuda_runtime.h>
#include <cuda_fp16.h>
#include <cstdint>

// ============================================================
// PINN fwd + 1st/2nd derivatives via mma.sync (HMMA) fp16
//   CTA: 16 samples, 512 threads / 16 warps.
//   Warp w: j-tile pair wp=w>>1 (32 M-rows) x ct-parity h=w&1.
//   State S single fp16, double-buffered. W = Whi + Wlo (fp16 each).
//   Hi pass on all 7 quantities; Wlo correction pass ONLY on the h
//   channel (q=0) — J/T channel error is already dominated by fp16
//   state quantization, h errors are the ones that amplify.
// ============================================================

#define THREADS 512
#define SB 16
#define BROW 240              // bytes per state row (112*2 = 224 + 16 pad)
#define BUFSZ (256 * BROW)    // 61440 per buffer

#define SM_B0 0
#define SM_B1 BUFSZ
#define SM_W4   (2 * BUFSZ)         // 122880 : w4t[o][i] f32, 2048 B
#define SM_BIAS (SM_W4 + 2048)      // 124928 : b1,b2,b3 f32, 3072 B (reused as reduce scratch)
#define SM_TOTAL (SM_BIAS + 3072)   // 128000
// final-layer fp32 state overlays both buffers: S3f[c][i], stride 1040 B
#define S3STRIDE 260                // floats per row (256 + 4 pad)

// fragment-major weight images: [L][jt(16)][kb(8)][lane(32)][8 x u32] fp16x2
__device__ uint32_t g_WfH[3 * 16 * 8 * 32 * 8];
__device__ uint32_t g_WfL[3 * 16 * 8 * 32 * 8];

__device__ __forceinline__ uint32_t smem_u32(const void* p) {
    uint32_t a;
    asm("{ .reg .u64 t; cvta.to.shared.u64 t, %1; cvt.u32.u64 %0, t; }"
        : "=r"(a) : "l"(p));
    return a;
}
__device__ __forceinline__ void ldmB4(uint32_t* b, uint32_t addr) {
    asm volatile("ldmatrix.sync.aligned.m8n8.x4.trans.shared.b16 {%0,%1,%2,%3}, [%4];"
                 : "=r"(b[0]), "=r"(b[1]), "=r"(b[2]), "=r"(b[3]) : "r"(addr));
}
__device__ __forceinline__ void mma4(float* d, uint4 a, uint32_t b0, uint32_t b1) {
    asm volatile(
        "mma.sync.aligned.m16n8k16.row.col.f32.f16.f16.f32 "
        "{%0,%1,%2,%3}, {%4,%5,%6,%7}, {%8,%9}, {%0,%1,%2,%3};"
        : "+f"(d[0]), "+f"(d[1]), "+f"(d[2]), "+f"(d[3])
        : "r"(a.x), "r"(a.y), "r"(a.z), "r"(a.w), "r"(b0), "r"(b1));
}
__device__ __forceinline__ uint32_t pk2h(float a, float b) {
    __half2 h = __float22half2_rn(make_float2(a, b));
    return *reinterpret_cast<uint32_t*>(&h);
}

// ---------------- prep: W[L] (i-major) -> fragment-major fp16 hi/lo ------
__global__ void __launch_bounds__(256) prep_kernel(
    const float* __restrict__ W1, const float* __restrict__ W2,
    const float* __restrict__ W3)
{
    int idx = blockIdx.x * 256 + threadIdx.x;   // 0 .. 98303
    int L = idx / 32768;
    int rem = idx & 32767;
    int jt = rem >> 11;
    int kb = (rem >> 8) & 7;
    int lane = (rem >> 3) & 31;
    int r = rem & 7;
    int g = lane >> 2, tg = lane & 3;
    int kk = r >> 2, rr = r & 3;
    int j = jt * 16 + g + 8 * (rr & 1);
    int i = kb * 32 + kk * 16 + 8 * (rr >> 1) + 2 * tg;
    const float* W = (L == 0) ? W1 : ((L == 1) ? W2 : W3);
    float v0 = W[i * 256 + j];
    float v1 = W[(i + 1) * 256 + j];
    float h0 = __half2float(__float2half_rn(v0));
    float h1 = __half2float(__float2half_rn(v1));
    g_WfH[idx] = pk2h(v0, v1);
    g_WfL[idx] = pk2h(v0 - h0, v1 - h1);
}

// ---------------- main kernel ----------------
__global__ void __launch_bounds__(THREADS, 1) pinn_mma_kernel(
    const float* __restrict__ x,
    const float* __restrict__ W0, const float* __restrict__ b0_,
    const float* __restrict__ b1_, const float* __restrict__ b2_,
    const float* __restrict__ b3_,
    const float* __restrict__ W4, const float* __restrict__ b4,
    const float* __restrict__ lb, const float* __restrict__ ub,
    float* __restrict__ out, int N)
{
    extern __shared__ char sm[];
    const uint32_t smb = smem_u32(sm);
    const int tid  = threadIdx.x;
    const int warp = tid >> 5, lane = tid & 31;
    const int g = lane >> 2, tg = lane & 3;
    const int h  = warp & 1;             // ct parity = sample half
    const int wp = warp >> 1;            // j-tile pair index (0..7)
    const int s0 = blockIdx.x * SB;

    // stage W4 transposed (w4t[o][i]) and hidden biases
    ((float*)(sm + SM_W4))[(tid & 1) * 256 + (tid >> 1)] = W4[tid];
    if (tid < 256) {
        ((float*)(sm + SM_BIAS))[tid]       = b1_[tid];
        ((float*)(sm + SM_BIAS))[256 + tid] = b2_[tid];
        ((float*)(sm + SM_BIAS))[512 + tid] = b3_[tid];
    }

    // ---------- layer 0: 3 -> 256 (SIMT), write fp16 state to buf0 -------
    {
        float lbv[3], sk[3];
#pragma unroll
        for (int k = 0; k < 3; k++) { lbv[k] = lb[k]; sk[k] = 2.0f / (ub[k] - lb[k]); }
        const int j = tid & 255;
        const int hh = tid >> 8;         // sample-half split across 512 threads
        float w[3];
#pragma unroll
        for (int k = 0; k < 3; k++) w[k] = W0[k * 256 + j];
        const float bj = b0_[j];
        float zj[3], Szl = 0.0f;
#pragma unroll
        for (int k = 0; k < 3; k++) { zj[k] = w[k] * sk[k]; Szl += zj[k]; }
#pragma unroll
        for (int spp = 0; spp < 4; spp++) {
            const int sp = hh * 4 + spp;
            float v[2][7];
#pragma unroll
            for (int p = 0; p < 2; p++) {
                const int s = 2 * sp + p;
                float xn0 = sk[0] * (x[(s0 + s) * 3 + 0] - lbv[0]) - 1.0f;
                float xn1 = sk[1] * (x[(s0 + s) * 3 + 1] - lbv[1]) - 1.0f;
                float xn2 = sk[2] * (x[(s0 + s) * 3 + 2] - lbv[2]) - 1.0f;
                float z = bj + w[0] * xn0 + w[1] * xn1 + w[2] * xn2;
                float t = tanhf(z);
                float gg = 1.0f - t * t;
                float u = -2.0f * t * gg * Szl;
                v[p][0] = t;
#pragma unroll
                for (int k = 0; k < 3; k++) { v[p][1 + k] = gg * zj[k]; v[p][4 + k] = u * zj[k]; }
            }
#pragma unroll
            for (int q = 0; q < 7; q++) {
                const int off = j * BROW + 32 * q + 4 * sp;   // col = 16q + 2sp
                *(uint32_t*)(sm + SM_B0 + off) = pk2h(v[0][q], v[1][q]);
            }
        }
    }
    __syncthreads();

    // ---------- hidden layers 1..3 via mma.sync ----------
#pragma unroll 1
    for (int L = 0; L < 3; L++) {
        const uint32_t bufR = smb + ((L == 1) ? SM_B1 : SM_B0);
        const uint32_t bufW = smb + ((L == 0) ? SM_B1 : SM_B0);

        float acc[2][7][4];                  // [j-tile][quantity][frag]
#pragma unroll
        for (int jj = 0; jj < 2; jj++)
#pragma unroll
            for (int q = 0; q < 7; q++)
#pragma unroll
                for (int d = 0; d < 4; d++) acc[jj][q][d] = 0.0f;

#pragma unroll 1
        for (int kb = 0; kb < 8; kb++) {
            // fragment-major A: 2x LDG.128 per (jj, hi/lo)
            uint4 ah0[2], ah1[2], al0[2], al1[2];
#pragma unroll
            for (int jj = 0; jj < 2; jj++) {
                const int base =
                    (((L * 16 + (wp * 2 + jj)) * 8 + kb) * 32 + lane) * 2;
                const uint4* FH = reinterpret_cast<const uint4*>(g_WfH);
                const uint4* FL = reinterpret_cast<const uint4*>(g_WfL);
                ah0[jj] = FH[base];
                ah1[jj] = FH[base + 1];
                al0[jj] = FL[base];
                al1[jj] = FL[base + 1];
            }
            // all 7 B fragments for this kb up front (28 regs)
            uint32_t b[7][4];
#pragma unroll
            for (int q = 0; q < 7; q++) {
                const int ct = 2 * q + h;
                const uint32_t baddr = bufR +
                    (uint32_t)(kb * 32 * BROW) + (uint32_t)(lane * BROW) + ct * 16;
                ldmB4(b[q], baddr);
            }
            // hi passes: all 7 quantities, reuse distance 14
#pragma unroll
            for (int q = 0; q < 7; q++) {
                mma4(acc[0][q], ah0[0], b[q][0], b[q][1]);
                mma4(acc[1][q], ah0[1], b[q][0], b[q][1]);
            }
#pragma unroll
            for (int q = 0; q < 7; q++) {
                mma4(acc[0][q], ah1[0], b[q][2], b[q][3]);
                mma4(acc[1][q], ah1[1], b[q][2], b[q][3]);
            }
            // lo correction pass: ONLY the h channel (q=0)
            mma4(acc[0][0], al0[0], b[0][0], b[0][1]);
            mma4(acc[1][0], al0[1], b[0][0], b[0][1]);
            mma4(acc[0][0], al1[0], b[0][2], b[0][3]);
            mma4(acc[1][0], al1[1], b[0][2], b[0][3]);
        }

        const bool last = (L == 2);
        if (last) __syncthreads();   // S3f overlays buffers; all reads must drain

        // ---------- elementwise (thread-local; writes bufW != bufR) ------
        const float* bias = (const float*)(sm + SM_BIAS) + L * 256;
        const int se = 8 * h + 2 * tg;       // even sample index owned by this thread
#pragma unroll
        for (int jj = 0; jj < 2; jj++) {
#pragma unroll
            for (int r = 0; r < 2; r++) {
                const int j = (wp * 2 + jj) * 16 + g + 8 * r;
                const float bj = bias[j];
                float v[2][7];
#pragma unroll
                for (int p = 0; p < 2; p++) {
                    const int d = 2 * r + p;
                    float zh = acc[jj][0][d] + bj;
                    float z0 = acc[jj][1][d];
                    float z1 = acc[jj][2][d];
                    float z2 = acc[jj][3][d];
                    float t0 = acc[jj][4][d];
                    float t1 = acc[jj][5][d];
                    float t2 = acc[jj][6][d];
                    float t = tanhf(zh);
                    float gg = 1.0f - t * t;
                    float Sz = z0 + z1 + z2;
                    float u = -2.0f * t * gg * Sz;
                    v[p][0] = t;
                    v[p][1] = gg * z0; v[p][2] = gg * z1; v[p][3] = gg * z2;
                    v[p][4] = u * z0 + gg * t0;
                    v[p][5] = u * z1 + gg * t1;
                    v[p][6] = u * z2 + gg * t2;
                }
                if (!last) {
#pragma unroll
                    for (int q = 0; q < 7; q++) {
                        const int off = j * BROW + (16 * q + se) * 2;
                        *(uint32_t*)(bufW - smb + sm + off) = pk2h(v[0][q], v[1][q]);
                    }
                } else {
#pragma unroll
                    for (int q = 0; q < 7; q++) {
                        ((float*)sm)[(16 * q + se) * S3STRIDE + j]     = v[0][q];
                        ((float*)sm)[(16 * q + se + 1) * S3STRIDE + j] = v[1][q];
                    }
                }
            }
        }
        __syncthreads();
    }

    // ---------- final layer: 256 -> 2, 2-way split-K over 448 threads ----
    float* red = (float*)(sm + SM_BIAS);     // biases no longer needed
    if (tid < 448) {
        const int c = tid >> 2, r2 = tid & 3;
        const int o = r2 & 1, kh = r2 >> 1;
        const float4* row = reinterpret_cast<const float4*>(
            sm + (size_t)c * (S3STRIDE * 4)) + kh * 32;
        const float4* wr = reinterpret_cast<const float4*>(
            sm + SM_W4 + o * 1024) + kh * 32;
        float sum = 0.0f;
#pragma unroll 8
        for (int i4 = 0; i4 < 32; i4++) {
            float4 a = row[i4];
            float4 b = wr[i4];
            sum += a.x * b.x + a.y * b.y + a.z * b.z + a.w * b.w;
        }
        red[tid] = sum;
    }
    __syncthreads();
    if (tid < 224) {
        const int c = tid >> 1, o = tid & 1;
        float sum = red[c * 4 + o] + red[c * 4 + 2 + o];
        const int q = c >> 4, s = c & 15;
        const int n = s0 + s;
        if (q == 0) {
            out[n * 2 + o] = sum + b4[o];
        } else if (q < 4) {
            out[2 * N + o * 3 * N + n * 3 + (q - 1)] = sum;
        } else {
            out[8 * N + o * 3 * N + n * 3 + (q - 4)] = sum;
        }
    }
}

extern "C" void kernel_launch(void* const* d_in, const int* in_sizes, int n_in,
                              void* d_out, int out_size)
{
    const float* x  = (const float*)d_in[0];
    const float* W0 = (const float*)d_in[1];
    const float* b0 = (const float*)d_in[2];
    const float* W1 = (const float*)d_in[3];
    const float* b1 = (const float*)d_in[4];
    const float* W2 = (const float*)d_in[5];
    const float* b2 = (const float*)d_in[6];
    const float* W3 = (const float*)d_in[7];
    const float* b3 = (const float*)d_in[8];
    const float* W4 = (const float*)d_in[9];
    const float* b4 = (const float*)d_in[10];
    const float* lb = (const float*)d_in[11];
    const float* ub = (const float*)d_in[12];
    float* out = (float*)d_out;

    const int N = in_sizes[0] / 3;          // 32768

    prep_kernel<<<3 * 32768 / 256, 256>>>(W1, W2, W3);

    cudaFuncSetAttribute(pinn_mma_kernel,
                         cudaFuncAttributeMaxDynamicSharedMemorySize, SM_TOTAL);
    pinn_mma_kernel<<<N / SB, THREADS, SM_TOTAL>>>(
        x, W0, b0, b1, b2, b3, W4, b4, lb, ub, out, N);
}

// round 17
// speedup vs baseline: 3.0706x; 1.1861x over previous
#include <cuda_runtime.h>
#include <cuda_fp16.h>
#include <cstdint>

// ============================================================
// PINN fwd + 1st/2nd derivatives via mma.sync (HMMA) fp16
//   CTA: 16 samples, 512 threads / 16 warps.
//   Warp w: j-tile pair wp=w>>1 (32 M-rows) x ct-parity h=w&1.
//   8 state channels: q0=h_hi, q1..3=J, q4..6=T, q7=h_lo (residual).
//   W stored fp16 (hi only). z_h = W*h_hi + W*h_lo -> h interface
//   ~2^-22; J/T channels carry the same 2^-11 budget as before.
//   Single fp16 state, double-buffered; one barrier per layer.
// ============================================================

#define THREADS 512
#define SB 16
#define BROW 272              // bytes per state row (128*2 = 256 + 16 pad)
#define BUFSZ (256 * BROW)    // 69632 per buffer

#define SM_B0 0
#define SM_B1 BUFSZ
#define SM_W4   (2 * BUFSZ)         // 139264 : w4t[o][i] f32, 2048 B
#define SM_BIAS (SM_W4 + 2048)      // 141312 : b1,b2,b3 f32, 3072 B (reused as reduce scratch)
#define SM_TOTAL (SM_BIAS + 3072)   // 144384
// final-layer fp32 state overlays buffers: S3f[c][i], stride 1040 B
#define S3STRIDE 260                // floats per row (256 + 4 pad)

// fragment-major fp16 weight image: [L][jt(16)][kb(8)][lane(32)][8 x u32]
__device__ uint32_t g_WfH[3 * 16 * 8 * 32 * 8];

__device__ __forceinline__ uint32_t smem_u32(const void* p) {
    uint32_t a;
    asm("{ .reg .u64 t; cvta.to.shared.u64 t, %1; cvt.u32.u64 %0, t; }"
        : "=r"(a) : "l"(p));
    return a;
}
__device__ __forceinline__ void ldmB4(uint32_t* b, uint32_t addr) {
    asm volatile("ldmatrix.sync.aligned.m8n8.x4.trans.shared.b16 {%0,%1,%2,%3}, [%4];"
                 : "=r"(b[0]), "=r"(b[1]), "=r"(b[2]), "=r"(b[3]) : "r"(addr));
}
__device__ __forceinline__ void mma4(float* d, uint4 a, uint32_t b0, uint32_t b1) {
    asm volatile(
        "mma.sync.aligned.m16n8k16.row.col.f32.f16.f16.f32 "
        "{%0,%1,%2,%3}, {%4,%5,%6,%7}, {%8,%9}, {%0,%1,%2,%3};"
        : "+f"(d[0]), "+f"(d[1]), "+f"(d[2]), "+f"(d[3])
        : "r"(a.x), "r"(a.y), "r"(a.z), "r"(a.w), "r"(b0), "r"(b1));
}
__device__ __forceinline__ uint32_t pk2h(float a, float b) {
    __half2 h = __float22half2_rn(make_float2(a, b));
    return *reinterpret_cast<uint32_t*>(&h);
}
__device__ __forceinline__ float f16r(float a) {   // fp16 rounding
    return __half2float(__float2half_rn(a));
}

// ---------------- prep: W[L] (i-major) -> fragment-major fp16 ------------
__global__ void __launch_bounds__(256) prep_kernel(
    const float* __restrict__ W1, const float* __restrict__ W2,
    const float* __restrict__ W3)
{
    int idx = blockIdx.x * 256 + threadIdx.x;   // 0 .. 98303
    int L = idx / 32768;
    int rem = idx & 32767;
    int jt = rem >> 11;
    int kb = (rem >> 8) & 7;
    int lane = (rem >> 3) & 31;
    int r = rem & 7;
    int g = lane >> 2, tg = lane & 3;
    int kk = r >> 2, rr = r & 3;
    int j = jt * 16 + g + 8 * (rr & 1);
    int i = kb * 32 + kk * 16 + 8 * (rr >> 1) + 2 * tg;
    const float* W = (L == 0) ? W1 : ((L == 1) ? W2 : W3);
    g_WfH[idx] = pk2h(W[i * 256 + j], W[(i + 1) * 256 + j]);
}

// ---------------- main kernel ----------------
__global__ void __launch_bounds__(THREADS, 1) pinn_mma_kernel(
    const float* __restrict__ x,
    const float* __restrict__ W0, const float* __restrict__ b0_,
    const float* __restrict__ b1_, const float* __restrict__ b2_,
    const float* __restrict__ b3_,
    const float* __restrict__ W4, const float* __restrict__ b4,
    const float* __restrict__ lb, const float* __restrict__ ub,
    float* __restrict__ out, int N)
{
    extern __shared__ char sm[];
    const uint32_t smb = smem_u32(sm);
    const int tid  = threadIdx.x;
    const int warp = tid >> 5, lane = tid & 31;
    const int g = lane >> 2, tg = lane & 3;
    const int h  = warp & 1;             // ct parity = sample half
    const int wp = warp >> 1;            // j-tile pair index (0..7)
    const int s0 = blockIdx.x * SB;

    // stage W4 transposed (w4t[o][i]) and hidden biases
    ((float*)(sm + SM_W4))[(tid & 1) * 256 + (tid >> 1)] = W4[tid];
    if (tid < 256) {
        ((float*)(sm + SM_BIAS))[tid]       = b1_[tid];
        ((float*)(sm + SM_BIAS))[256 + tid] = b2_[tid];
        ((float*)(sm + SM_BIAS))[512 + tid] = b3_[tid];
    }

    // ---------- layer 0: 3 -> 256 (SIMT), write fp16 state to buf0 -------
    {
        float lbv[3], sk[3];
#pragma unroll
        for (int k = 0; k < 3; k++) { lbv[k] = lb[k]; sk[k] = 2.0f / (ub[k] - lb[k]); }
        const int j = tid & 255;
        const int hh = tid >> 8;         // sample-half split across 512 threads
        float w[3];
#pragma unroll
        for (int k = 0; k < 3; k++) w[k] = W0[k * 256 + j];
        const float bj = b0_[j];
        float zj[3], Szl = 0.0f;
#pragma unroll
        for (int k = 0; k < 3; k++) { zj[k] = w[k] * sk[k]; Szl += zj[k]; }
#pragma unroll
        for (int spp = 0; spp < 4; spp++) {
            const int sp = hh * 4 + spp;
            float v[2][7];
#pragma unroll
            for (int p = 0; p < 2; p++) {
                const int s = 2 * sp + p;
                float xn0 = sk[0] * (x[(s0 + s) * 3 + 0] - lbv[0]) - 1.0f;
                float xn1 = sk[1] * (x[(s0 + s) * 3 + 1] - lbv[1]) - 1.0f;
                float xn2 = sk[2] * (x[(s0 + s) * 3 + 2] - lbv[2]) - 1.0f;
                float z = bj + w[0] * xn0 + w[1] * xn1 + w[2] * xn2;
                float t = tanhf(z);
                float gg = 1.0f - t * t;
                float u = -2.0f * t * gg * Szl;
                v[p][0] = t;
#pragma unroll
                for (int k = 0; k < 3; k++) { v[p][1 + k] = gg * zj[k]; v[p][4 + k] = u * zj[k]; }
            }
#pragma unroll
            for (int q = 0; q < 7; q++) {
                const int off = j * BROW + 32 * q + 4 * sp;   // col = 16q + 2sp
                *(uint32_t*)(sm + SM_B0 + off) = pk2h(v[0][q], v[1][q]);
            }
            // channel 7: h residual (t - fp16(t))
            *(uint32_t*)(sm + SM_B0 + j * BROW + 224 + 4 * sp) =
                pk2h(v[0][0] - f16r(v[0][0]), v[1][0] - f16r(v[1][0]));
        }
    }
    __syncthreads();

    // ---------- hidden layers 1..3 via mma.sync ----------
#pragma unroll 1
    for (int L = 0; L < 3; L++) {
        const uint32_t bufR = smb + ((L == 1) ? SM_B1 : SM_B0);
        const uint32_t bufW = smb + ((L == 0) ? SM_B1 : SM_B0);

        float acc[2][8][4];                  // [j-tile][channel][frag]
#pragma unroll
        for (int jj = 0; jj < 2; jj++)
#pragma unroll
            for (int q = 0; q < 8; q++)
#pragma unroll
                for (int d = 0; d < 4; d++) acc[jj][q][d] = 0.0f;

#pragma unroll 1
        for (int kb = 0; kb < 8; kb++) {
            // fragment-major A (hi only): 2x LDG.128 per jj
            uint4 ah0[2], ah1[2];
#pragma unroll
            for (int jj = 0; jj < 2; jj++) {
                const int base =
                    (((L * 16 + (wp * 2 + jj)) * 8 + kb) * 32 + lane) * 2;
                const uint4* FH = reinterpret_cast<const uint4*>(g_WfH);
                ah0[jj] = FH[base];
                ah1[jj] = FH[base + 1];
            }
            // all 8 B fragments for this kb up front (32 regs)
            uint32_t b[8][4];
#pragma unroll
            for (int q = 0; q < 8; q++) {
                const int ct = 2 * q + h;
                const uint32_t baddr = bufR +
                    (uint32_t)(kb * 32 * BROW) + (uint32_t)(lane * BROW) + ct * 16;
                ldmB4(b[q], baddr);
            }
            // pass-major issue: reuse distance = 16 MMAs per accumulator
#pragma unroll
            for (int q = 0; q < 8; q++) {
                mma4(acc[0][q], ah0[0], b[q][0], b[q][1]);
                mma4(acc[1][q], ah0[1], b[q][0], b[q][1]);
            }
#pragma unroll
            for (int q = 0; q < 8; q++) {
                mma4(acc[0][q], ah1[0], b[q][2], b[q][3]);
                mma4(acc[1][q], ah1[1], b[q][2], b[q][3]);
            }
        }

        const bool last = (L == 2);
        if (last) __syncthreads();   // S3f overlays buffers; all reads must drain

        // ---------- elementwise (thread-local; writes bufW != bufR) ------
        const float* bias = (const float*)(sm + SM_BIAS) + L * 256;
        const int se = 8 * h + 2 * tg;       // even sample index owned by this thread
#pragma unroll
        for (int jj = 0; jj < 2; jj++) {
#pragma unroll
            for (int r = 0; r < 2; r++) {
                const int j = (wp * 2 + jj) * 16 + g + 8 * r;
                const float bj = bias[j];
                float v[2][7];
#pragma unroll
                for (int p = 0; p < 2; p++) {
                    const int d = 2 * r + p;
                    float zh = acc[jj][0][d] + acc[jj][7][d] + bj;  // hi + lo
                    float z0 = acc[jj][1][d];
                    float z1 = acc[jj][2][d];
                    float z2 = acc[jj][3][d];
                    float t0 = acc[jj][4][d];
                    float t1 = acc[jj][5][d];
                    float t2 = acc[jj][6][d];
                    float t = tanhf(zh);
                    float gg = 1.0f - t * t;
                    float Sz = z0 + z1 + z2;
                    float u = -2.0f * t * gg * Sz;
                    v[p][0] = t;
                    v[p][1] = gg * z0; v[p][2] = gg * z1; v[p][3] = gg * z2;
                    v[p][4] = u * z0 + gg * t0;
                    v[p][5] = u * z1 + gg * t1;
                    v[p][6] = u * z2 + gg * t2;
                }
                if (!last) {
#pragma unroll
                    for (int q = 0; q < 7; q++) {
                        const int off = j * BROW + (16 * q + se) * 2;
                        *(uint32_t*)(bufW - smb + sm + off) = pk2h(v[0][q], v[1][q]);
                    }
                    // channel 7: h residual
                    *(uint32_t*)(bufW - smb + sm + j * BROW + (112 + se) * 2) =
                        pk2h(v[0][0] - f16r(v[0][0]), v[1][0] - f16r(v[1][0]));
                } else {
#pragma unroll
                    for (int q = 0; q < 7; q++) {
                        ((float*)sm)[(16 * q + se) * S3STRIDE + j]     = v[0][q];
                        ((float*)sm)[(16 * q + se + 1) * S3STRIDE + j] = v[1][q];
                    }
                }
            }
        }
        __syncthreads();
    }

    // ---------- final layer: 256 -> 2, 2-way split-K over 448 threads ----
    float* red = (float*)(sm + SM_BIAS);     // biases no longer needed
    if (tid < 448) {
        const int c = tid >> 2, r2 = tid & 3;
        const int o = r2 & 1, kh = r2 >> 1;
        const float4* row = reinterpret_cast<const float4*>(
            sm + (size_t)c * (S3STRIDE * 4)) + kh * 32;
        const float4* wr = reinterpret_cast<const float4*>(
            sm + SM_W4 + o * 1024) + kh * 32;
        float sum = 0.0f;
#pragma unroll 8
        for (int i4 = 0; i4 < 32; i4++) {
            float4 a = row[i4];
            float4 b = wr[i4];
            sum += a.x * b.x + a.y * b.y + a.z * b.z + a.w * b.w;
        }
        red[tid] = sum;
    }
    __syncthreads();
    if (tid < 224) {
        const int c = tid >> 1, o = tid & 1;
        float sum = red[c * 4 + o] + red[c * 4 + 2 + o];
        const int q = c >> 4, s = c & 15;
        const int n = s0 + s;
        if (q == 0) {
            out[n * 2 + o] = sum + b4[o];
        } else if (q < 4) {
            out[2 * N + o * 3 * N + n * 3 + (q - 1)] = sum;
        } else {
            out[8 * N + o * 3 * N + n * 3 + (q - 4)] = sum;
        }
    }
}

extern "C" void kernel_launch(void* const* d_in, const int* in_sizes, int n_in,
                              void* d_out, int out_size)
{
    const float* x  = (const float*)d_in[0];
    const float* W0 = (const float*)d_in[1];
    const float* b0 = (const float*)d_in[2];
    const float* W1 = (const float*)d_in[3];
    const float* b1 = (const float*)d_in[4];
    const float* W2 = (const float*)d_in[5];
    const float* b2 = (const float*)d_in[6];
    const float* W3 = (const float*)d_in[7];
    const float* b3 = (const float*)d_in[8];
    const float* W4 = (const float*)d_in[9];
    const float* b4 = (const float*)d_in[10];
    const float* lb = (const float*)d_in[11];
    const float* ub = (const float*)d_in[12];
    float* out = (float*)d_out;

    const int N = in_sizes[0] / 3;          // 32768

    prep_kernel<<<3 * 32768 / 256, 256>>>(W1, W2, W3);

    cudaFuncSetAttribute(pinn_mma_kernel,
                         cudaFuncAttributeMaxDynamicSharedMemorySize, SM_TOTAL);
    pinn_mma_kernel<<<N / SB, THREADS, SM_TOTAL>>>(
        x, W0, b0, b1, b2, b3, W4, b4, lb, ub, out, N);
}